// round 16
// baseline (speedup 1.0000x reference)
#include <cuda_runtime.h>
#include <cuda_bf16.h>

#define THREADS 128
#define PAIRS 2                       // warp pairs per CTA
#define ROWS 8                        // edges per tile

__device__ int g_idx_is64;

static __device__ __forceinline__ unsigned int pack_bf16x2(float lo, float hi) {
    __nv_bfloat162 hh = __float22bfloat162_rn(make_float2(lo, hi));
    return *reinterpret_cast<unsigned int*>(&hh);
}
static __device__ __forceinline__ float2 unpack_bf16x2(unsigned int u) {
    float2 r;
    r.x = __uint_as_float(u << 16);
    r.y = __uint_as_float(u & 0xffff0000u);
    return r;
}

// ---------------- prep: zero output + detect index dtype ----------------
__global__ void prep_kernel(float4* out, int n4, const unsigned int* idxw, int n_pairs) {
    int i = blockIdx.x * blockDim.x + threadIdx.x;
    int stride = gridDim.x * blockDim.x;
    for (; i < n4; i += stride) out[i] = make_float4(0.f, 0.f, 0.f, 0.f);
    if (blockIdx.x == 0) {
        __shared__ unsigned int acc;
        if (threadIdx.x == 0) acc = 0u;
        __syncthreads();
        unsigned int v = 0u;
        for (int j = threadIdx.x; j < n_pairs; j += blockDim.x) v |= idxw[2 * j + 1];
        atomicOr(&acc, v);
        __syncthreads();
        if (threadIdx.x == 0) g_idx_is64 = (acc == 0u) ? 1 : 0;
    }
}

// ---------------- fused gate-GEMM + v4 register scatter, direct-LDG ----------------
__global__ __launch_bounds__(THREADS, 4)
void fused_gate_scatter(const float* __restrict__ x,
                        const float* __restrict__ Wg,
                        const float* __restrict__ lparam,
                        const void* __restrict__ index,
                        float* __restrict__ out,
                        long long E, int num_tiles)
{
    const int tid  = threadIdx.x;
    const int wid  = tid >> 5;
    const int lane = tid & 31;
    const int g    = lane >> 2;      // 0..7 : edge row within tile
    const int q    = lane & 3;       // 0..3
    const int pair = wid >> 1;       // 0..1
    const int h    = wid & 1;        // 0/1 : gate-col half

    const int   is64 = g_idx_is64;
    const float lp   = fabsf(__ldg(lparam));

    // ---- persistent B fragments: cols n = h*64 + m*8 + g, m = 0..7 ----
    unsigned int Breg[8][4][2];
    #pragma unroll
    for (int m = 0; m < 8; m++) {
        const int n = h * 64 + m * 8 + g;
        #pragma unroll
        for (int ks = 0; ks < 4; ks++) {
            const int k = ks * 16 + q * 2;
            float2 w0 = __ldg(reinterpret_cast<const float2*>(Wg + n * 64 + k));
            float2 w1 = __ldg(reinterpret_cast<const float2*>(Wg + n * 64 + k + 8));
            Breg[m][ks][0] = pack_bf16x2(w0.x, w0.y);
            Breg[m][ks][1] = pack_bf16x2(w1.x, w1.y);
        }
    }

    const int S  = (int)gridDim.x * PAIRS;
    const int pg = (int)blockIdx.x * PAIRS + pair;

    int it = 0;
    for (int tcur = pg; tcur < num_tiles; tcur += S, it++) {
        // loose pair rendezvous every 8 tiles: bounds drift so the partner's
        // duplicate row reads stay L1-resident (both warps have identical trip counts)
        if ((it & 7) == 0)
            asm volatile("bar.sync %0, 64;" :: "r"(pair + 1) : "memory");

        const long long eg = (long long)tcur * ROWS + g;
        const bool valid = (eg < E);
        const float* Xrow = x + eg * 128;

        long long nd = 0;
        if (valid)
            nd = is64 ? ((const long long*)index)[eg]
                      : (long long)((const int*)index)[eg];

        // ---- direct global load + convert A ----
        unsigned int ap0[4], ap1[4], ap2[4], ap3[4];   // packed bf16
        float2 Fh_lo[4], Fh_hi[4];                     // fp32 of patch h
        #pragma unroll
        for (int ks = 0; ks < 4; ks++) {
            const int kb = ks * 16 + q * 2;
            float2 f0, f1, f2, f3;
            if (valid) {
                f0 = __ldg(reinterpret_cast<const float2*>(Xrow + kb));        // patch0
                f1 = __ldg(reinterpret_cast<const float2*>(Xrow + 64 + kb));   // patch1
                f2 = __ldg(reinterpret_cast<const float2*>(Xrow + kb + 8));
                f3 = __ldg(reinterpret_cast<const float2*>(Xrow + 64 + kb + 8));
            } else {
                f0 = make_float2(0.f, 0.f); f1 = f0; f2 = f0; f3 = f0;
            }
            ap0[ks] = pack_bf16x2(f0.x, f0.y);
            ap1[ks] = pack_bf16x2(f1.x, f1.y);
            ap2[ks] = pack_bf16x2(f2.x, f2.y);
            ap3[ks] = pack_bf16x2(f3.x, f3.y);
            Fh_lo[ks] = h ? f1 : f0;
            Fh_hi[ks] = h ? f3 : f2;
        }

        float* nrow = out + nd * 128 + h * 64;

        // ---- two N-passes: MMA (4 m) -> epilogue -> quad-shuffle -> RED.v4 ----
        #pragma unroll
        for (int pass = 0; pass < 2; pass++) {
            float acc[4][4];
            #pragma unroll
            for (int j = 0; j < 4; j++) {
                acc[j][0] = 0.f; acc[j][1] = 0.f; acc[j][2] = 0.f; acc[j][3] = 0.f;
            }
            #pragma unroll
            for (int ks = 0; ks < 4; ks++) {
                #pragma unroll
                for (int j = 0; j < 4; j++) {
                    const int m = pass * 4 + j;
                    asm volatile(
                        "mma.sync.aligned.m16n8k16.row.col.f32.bf16.bf16.f32 "
                        "{%0,%1,%2,%3}, {%4,%5,%6,%7}, {%8,%9}, {%0,%1,%2,%3};"
                        : "+f"(acc[j][0]), "+f"(acc[j][1]),
                          "+f"(acc[j][2]), "+f"(acc[j][3])
                        : "r"(ap0[ks]), "r"(ap1[ks]), "r"(ap2[ks]), "r"(ap3[ks]),
                          "r"(Breg[m][ks][0]), "r"(Breg[m][ks][1]));
                }
            }
            float2 V[4];
            #pragma unroll
            for (int j = 0; j < 4; j++) {
                const int m  = pass * 4 + j;      // out col o = h*64 + m*8 + q*2
                const int ks = m >> 1;
                float2 eh = (m & 1) ? Fh_hi[ks] : Fh_lo[ks];
                unsigned int u0 = (m & 1) ? ap2[ks] : ap0[ks];
                unsigned int u1 = (m & 1) ? ap3[ks] : ap1[ks];
                float2 ge0 = h ? unpack_bf16x2(u0) : eh;
                float2 ge1 = h ? eh : unpack_bf16x2(u1);
                float sx = ge0.x * __saturatef(acc[j][0]) + ge1.x * __saturatef(acc[j][2]);
                float sy = ge0.y * __saturatef(acc[j][1]) + ge1.y * __saturatef(acc[j][3]);
                V[j].x = fmaf(lp, sx, eh.x);
                V[j].y = fmaf(lp, sy, eh.y);
            }
            #pragma unroll
            for (int t2 = 0; t2 < 2; t2++) {
                const int j0 = 2 * t2, j1 = 2 * t2 + 1;
                float2 mine = (q & 1) ? V[j0] : V[j1];
                float ox = __shfl_xor_sync(0xffffffffu, mine.x, 1);
                float oy = __shfl_xor_sync(0xffffffffu, mine.y, 1);
                float2 keep = (q & 1) ? V[j1] : V[j0];
                float vx0 = (q & 1) ? ox : keep.x;
                float vy0 = (q & 1) ? oy : keep.y;
                float vx1 = (q & 1) ? keep.x : ox;
                float vy1 = (q & 1) ? keep.y : oy;
                const int mm = pass * 4 + j0 + (q & 1);   // row this thread reduces
                const int cb = mm * 8 + (q >> 1) * 4;     // col base within half
                if (valid) {
                    asm volatile("red.global.add.v4.f32 [%0], {%1,%2,%3,%4};"
                                 :: "l"(nrow + cb), "f"(vx0), "f"(vy0), "f"(vx1), "f"(vy1)
                                 : "memory");
                }
            }
        }
    }
}

// ---------------- launch ----------------
extern "C" void kernel_launch(void* const* d_in, const int* in_sizes, int n_in,
                              void* d_out, int out_size) {
    const float* x   = (const float*)d_in[0];
    const float* Wg  = (const float*)d_in[1];
    const float* lp  = (const float*)d_in[2];
    const void*  idx = d_in[3];

    long long E = (long long)in_sizes[0] / 128;
    int tiles = (int)((E + ROWS - 1) / ROWS);

    int dev = 0; cudaGetDevice(&dev);
    int sms = 148;
    cudaDeviceGetAttribute(&sms, cudaDevAttrMultiProcessorCount, dev);

    // prep: zero output + detect index dtype (single launch)
    int n4 = out_size / 4;
    long long npairs64 = E / 2; int npairs = npairs64 > 4096 ? 4096 : (int)npairs64;
    int zgrid = (n4 + 255) / 256;
    prep_kernel<<<zgrid, 256>>>((float4*)d_out, n4, (const unsigned int*)idx, npairs);

    int grid = 4 * sms;
    int maxg = (tiles + PAIRS - 1) / PAIRS;
    if (grid > maxg) grid = maxg;
    fused_gate_scatter<<<grid, THREADS>>>(x, Wg, lp, idx, (float*)d_out, E, tiles);
}